// round 1
// baseline (speedup 1.0000x reference)
#include <cuda_runtime.h>

// ---------------- problem constants ----------------
#define TOK    4096        // BATCH*SEQLEN
#define DMODEL 2048
#define DINNER 4096
#define NH     64
#define HD     64
#define NST    128
#define CDIM   4352        // DINNER + 2*NST
#define DPROJ  8512        // 2*DINNER + 2*NST + NH
#define SEQ    2048
#define CK     256         // chunk length
#define NCC    16          // BATCH * (SEQ/CK) total chunks

// ---------------- scratch (device globals; no allocation) ----------------
__device__ __align__(16) float g_zx  [(size_t)TOK*DPROJ];     // in_proj output
__device__ __align__(16) float g_xbc [(size_t)TOK*CDIM];      // conv+silu output
__device__ __align__(16) float g_Ct  [(size_t)NST*TOK];       // C transposed [n][t]
__device__ __align__(16) float g_dtv [(size_t)TOK*NH];        // softplus dt
__device__ __align__(16) float g_dacs[(size_t)NCC*NH*CK];     // cumsum(dt*A)
__device__ __align__(16) float g_cb  [(size_t)NCC*CK*CK];     // CB^T : [cc][s][l]
__device__ __align__(16) float g_st  [(size_t)NCC*NH*HD*NST]; // chunk states
__device__ __align__(16) float g_pv  [(size_t)NCC*NH*HD*NST]; // prefix states
__device__ __align__(16) float g_y   [(size_t)TOK*DINNER];    // gated y (pre-norm / normed)

// ---------------- generic fp32 GEMM: C[m,n] = sum_k A[m,k]*B[n,k] ----------------
// BM=128, BN=64, BK=8, 256 threads, 8x4 microtile. Dims must divide tiles (they do).
__global__ __launch_bounds__(256) void gemm_tn(
    const float* __restrict__ A, const float* __restrict__ B, float* __restrict__ C,
    int K, int lda, int ldb, int ldc, long aB, long bB, long cB)
{
    const float* Ab = A + (long)blockIdx.z * aB;
    const float* Bb = B + (long)blockIdx.z * bB;
    float*       Cb = C + (long)blockIdx.z * cB;

    __shared__ float As[8][128];
    __shared__ float Bs[8][64];

    int tid  = threadIdx.x;
    int m0   = blockIdx.y * 128, n0 = blockIdx.x * 64;
    int arow = tid >> 1, acol = (tid & 1) * 4;   // A: 128 rows x 8k, float4 each
    int brow = tid >> 2, bcol = (tid & 3) * 2;   // B: 64 rows x 8k, float2 each
    int tx   = tid & 15, ty = tid >> 4;

    float acc[8][4];
#pragma unroll
    for (int i = 0; i < 8; i++)
#pragma unroll
        for (int j = 0; j < 4; j++) acc[i][j] = 0.f;

    const float* aptr = Ab + (long)(m0 + arow) * lda + acol;
    const float* bptr = Bb + (long)(n0 + brow) * ldb + bcol;

    for (int k0 = 0; k0 < K; k0 += 8) {
        float4 av = *(const float4*)(aptr + k0);
        float2 bv = *(const float2*)(bptr + k0);
        As[acol + 0][arow] = av.x; As[acol + 1][arow] = av.y;
        As[acol + 2][arow] = av.z; As[acol + 3][arow] = av.w;
        Bs[bcol + 0][brow] = bv.x; Bs[bcol + 1][brow] = bv.y;
        __syncthreads();
#pragma unroll
        for (int kk = 0; kk < 8; kk++) {
            float a[8], b[4];
#pragma unroll
            for (int i = 0; i < 8; i++) a[i] = As[kk][ty * 8 + i];
#pragma unroll
            for (int j = 0; j < 4; j++) b[j] = Bs[kk][tx * 4 + j];
#pragma unroll
            for (int i = 0; i < 8; i++)
#pragma unroll
                for (int j = 0; j < 4; j++) acc[i][j] = fmaf(a[i], b[j], acc[i][j]);
        }
        __syncthreads();
    }
#pragma unroll
    for (int i = 0; i < 8; i++) {
        float* crow = Cb + (long)(m0 + ty * 8 + i) * ldc + n0 + tx * 4;
        *(float4*)crow = make_float4(acc[i][0], acc[i][1], acc[i][2], acc[i][3]);
    }
}

// ---------------- dt = softplus(raw + bias) ----------------
__global__ void k_dt(const float* __restrict__ zx, const float* __restrict__ dt_bias,
                     float* __restrict__ dt)
{
    int i = blockIdx.x * 256 + threadIdx.x;
    if (i >= TOK * NH) return;
    int t = i >> 6, h = i & 63;
    float v = zx[(long)t * DPROJ + (DINNER + CDIM) + h] + dt_bias[h];
    dt[i] = (v > 20.f) ? v : log1pf(expf(v));
}

// ---------------- causal conv1d(width 4) + bias + silu; also emit C^T ----------------
__global__ void k_conv(const float* __restrict__ zx, const float* __restrict__ w,
                       const float* __restrict__ bias, float* __restrict__ xbc,
                       float* __restrict__ Ct)
{
    long i = (long)blockIdx.x * 256 + threadIdx.x;
    if (i >= (long)TOK * CDIM) return;
    int t = (int)(i / CDIM), c = (int)(i % CDIM);
    int l = t & (SEQ - 1);
    float acc = bias[c];
#pragma unroll
    for (int k = 0; k < 4; k++) {
        int lt = l - 3 + k;
        if (lt >= 0)
            acc = fmaf(w[c * 4 + k], zx[(long)(t - 3 + k) * DPROJ + DINNER + c], acc);
    }
    float s = acc / (1.f + expf(-acc));
    xbc[i] = s;
    int n = c - (DINNER + NST);
    if (n >= 0) Ct[(long)n * TOK + t] = s;   // transposed copy of C for coalesced reads
}

// ---------------- per-(chunk,head) cumsum of dt*A ----------------
__global__ void k_dacs(const float* __restrict__ dt, const float* __restrict__ Alog,
                       float* __restrict__ dacs)
{
    int cc = blockIdx.x >> 6, h = blockIdx.x & 63;
    int s = threadIdx.x;
    int t = cc * CK + s;
    float a = -expf(Alog[h]);
    float v = dt[t * NH + h] * a;
    __shared__ float sm[CK];
    sm[s] = v; __syncthreads();
    for (int off = 1; off < CK; off <<= 1) {
        float tv = (s >= off) ? sm[s - off] : 0.f;
        __syncthreads();
        sm[s] += tv;
        __syncthreads();
    }
    dacs[(blockIdx.x << 8) + s] = sm[s];
}

// ---------------- states[h,p,n] = sum_s B[s,n]*exp(dAcs[255]-dAcs[s])*x[s,p]*dt[s] ----------------
__global__ __launch_bounds__(256) void k_states(const float* __restrict__ xbc,
        const float* __restrict__ dt, const float* __restrict__ dacs, float* __restrict__ st)
{
    int cc = blockIdx.x >> 6, h = blockIdx.x & 63;
    int tb = cc * CK;
    const float* dA = dacs + (blockIdx.x << 8);
    float dlast = dA[CK - 1];
    int tid = threadIdx.x;
    int p = tid & 63, ng = tid >> 6;   // thread: (p, n-group of 32)

    float acc[32];
#pragma unroll
    for (int j = 0; j < 32; j++) acc[j] = 0.f;

    __shared__ float sx[32][64];
    __shared__ float sb[32][128];
    for (int s0 = 0; s0 < CK; s0 += 32) {
        for (int i = tid; i < 32 * 64; i += 256) {
            int sl = i >> 6, pp = i & 63;
            int t = tb + s0 + sl;
            sx[sl][pp] = xbc[(long)t * CDIM + h * HD + pp] * dt[t * NH + h];
        }
        for (int i = tid; i < 32 * 128; i += 256) {
            int sl = i >> 7, nn = i & 127;
            int t = tb + s0 + sl;
            sb[sl][nn] = xbc[(long)t * CDIM + DINNER + nn] * __expf(dlast - dA[s0 + sl]);
        }
        __syncthreads();
#pragma unroll 4
        for (int sl = 0; sl < 32; sl++) {
            float a = sx[sl][p];
#pragma unroll
            for (int j = 0; j < 32; j++) acc[j] = fmaf(a, sb[sl][ng * 32 + j], acc[j]);
        }
        __syncthreads();
    }
    float* o = st + ((long)blockIdx.x << 13) + p * NST + ng * 32;
#pragma unroll
    for (int j = 0; j < 32; j += 4)
        *(float4*)(o + j) = make_float4(acc[j], acc[j + 1], acc[j + 2], acc[j + 3]);
}

// ---------------- sequential chunk scan (8 chunks per batch) ----------------
__global__ void k_scan(const float* __restrict__ st, const float* __restrict__ dacs,
                       float* __restrict__ pv)
{
    int b = blockIdx.x >> 6, h = blockIdx.x & 63;
    int tid = threadIdx.x;
    float carry[32];
#pragma unroll
    for (int j = 0; j < 32; j++) carry[j] = 0.f;
    for (int c = 0; c < 8; c++) {
        int cc = b * 8 + c;
        long base = ((long)(cc * 64 + h)) << 13;
        float dec = __expf(dacs[((cc * 64 + h) << 8) + CK - 1]);
#pragma unroll
        for (int j = 0; j < 32; j++) {
            long e = base + tid + j * 256;
            pv[e] = carry[j];                       // prev BEFORE update
            carry[j] = carry[j] * dec + st[e];
        }
    }
}

// ---------------- Y = Y_diag + Y_off + D*x, gated by silu(z) ----------------
__global__ __launch_bounds__(256) void k_y(const float* __restrict__ xbc,
        const float* __restrict__ zx, const float* __restrict__ dt,
        const float* __restrict__ dacs, const float* __restrict__ cb,
        const float* __restrict__ Ct, const float* __restrict__ pv,
        const float* __restrict__ Dsk, float* __restrict__ y)
{
    int cc = blockIdx.x >> 6, h = blockIdx.x & 63;
    int l = threadIdx.x;
    int tb = cc * CK;
    int t = tb + l;
    const float* dA = dacs + (blockIdx.x << 8);
    float dAl = dA[l];

    float acc[64];
#pragma unroll
    for (int p = 0; p < 64; p++) acc[p] = 0.f;

    __shared__ float sbuf[64 * 128];   // pass A: xdt tiles (4096); pass B: prev (8192)
    __shared__ float sdas[64];
    const float* cbb = cb + ((long)cc << 16);

    // ---- pass A: Y_diag (masked, s <= l) ----
    for (int s0 = 0; s0 < CK; s0 += 64) {
        for (int i = threadIdx.x; i < 64 * 64; i += 256) {
            int sl = i >> 6, pp = i & 63;
            int ts = tb + s0 + sl;
            sbuf[sl * 64 + pp] = xbc[(long)ts * CDIM + h * HD + pp] * dt[ts * NH + h];
        }
        if (threadIdx.x < 64) sdas[threadIdx.x] = dA[s0 + threadIdx.x];
        __syncthreads();
        if (s0 <= l) {
            int smax = min(64, l - s0 + 1);
            for (int sl = 0; sl < smax; sl++) {
                float w = __expf(dAl - sdas[sl]) * cbb[((s0 + sl) << 8) + l];
                const float4* r4 = (const float4*)(sbuf + sl * 64);
#pragma unroll
                for (int p4 = 0; p4 < 16; p4++) {
                    float4 v = r4[p4];
                    acc[p4 * 4 + 0] = fmaf(w, v.x, acc[p4 * 4 + 0]);
                    acc[p4 * 4 + 1] = fmaf(w, v.y, acc[p4 * 4 + 1]);
                    acc[p4 * 4 + 2] = fmaf(w, v.z, acc[p4 * 4 + 2]);
                    acc[p4 * 4 + 3] = fmaf(w, v.w, acc[p4 * 4 + 3]);
                }
            }
        }
        __syncthreads();
    }

    // ---- pass B: Y_off via prev-state staged in smem ----
    const float* pvb = pv + ((long)blockIdx.x << 13);
    for (int i = threadIdx.x; i < 8192; i += 256) sbuf[i] = pvb[i];
    __syncthreads();
    float el = __expf(dAl);
    const float4* pb4 = (const float4*)sbuf;
    for (int n4 = 0; n4 < 32; n4++) {
        float c0 = Ct[(long)(n4 * 4 + 0) * TOK + t] * el;
        float c1 = Ct[(long)(n4 * 4 + 1) * TOK + t] * el;
        float c2 = Ct[(long)(n4 * 4 + 2) * TOK + t] * el;
        float c3 = Ct[(long)(n4 * 4 + 3) * TOK + t] * el;
#pragma unroll
        for (int p = 0; p < 64; p++) {
            float4 v = pb4[p * 32 + n4];
            acc[p] = fmaf(c0, v.x, fmaf(c1, v.y, fmaf(c2, v.z, fmaf(c3, v.w, acc[p]))));
        }
    }

    // ---- epilogue: + D*x, gate with silu(z) ----
    float dsk = Dsk[h];
    const float4* xr = (const float4*)(xbc + (long)t * CDIM + h * HD);
    const float4* zr = (const float4*)(zx + (long)t * DPROJ + h * HD);
    float4* yr = (float4*)(y + (long)t * DINNER + h * HD);
#pragma unroll
    for (int p4 = 0; p4 < 16; p4++) {
        float4 xv = xr[p4], zv = zr[p4], o;
        float yv;
        yv = acc[p4 * 4 + 0] + xv.x * dsk; o.x = yv * (zv.x / (1.f + expf(-zv.x)));
        yv = acc[p4 * 4 + 1] + xv.y * dsk; o.y = yv * (zv.y / (1.f + expf(-zv.y)));
        yv = acc[p4 * 4 + 2] + xv.z * dsk; o.z = yv * (zv.z / (1.f + expf(-zv.z)));
        yv = acc[p4 * 4 + 3] + xv.w * dsk; o.w = yv * (zv.w / (1.f + expf(-zv.w)));
        yr[p4] = o;
    }
}

// ---------------- RMSNorm over full D_INNER (NGROUPS=1) ----------------
__global__ void k_rms(float* __restrict__ y, const float* __restrict__ nw)
{
    int t = blockIdx.x;
    float* row = y + (long)t * DINNER;
    float ss = 0.f;
    for (int i = threadIdx.x; i < DINNER; i += 256) { float v = row[i]; ss = fmaf(v, v, ss); }
    __shared__ float red[256];
    red[threadIdx.x] = ss; __syncthreads();
    for (int o = 128; o > 0; o >>= 1) {
        if (threadIdx.x < o) red[threadIdx.x] += red[threadIdx.x + o];
        __syncthreads();
    }
    float sc = rsqrtf(red[0] / (float)DINNER + 1e-5f);
    for (int i = threadIdx.x; i < DINNER; i += 256) row[i] = row[i] * sc * nw[i];
}

// ---------------- launch ----------------
extern "C" void kernel_launch(void* const* d_in, const int* in_sizes, int n_in,
                              void* d_out, int out_size)
{
    const float* u     = (const float*)d_in[0];
    const float* Win   = (const float*)d_in[1];
    const float* convw = (const float*)d_in[2];
    const float* convb = (const float*)d_in[3];
    const float* dtb   = (const float*)d_in[4];
    const float* Alog  = (const float*)d_in[5];
    const float* Dsk   = (const float*)d_in[6];
    const float* nw    = (const float*)d_in[7];
    const float* Wout  = (const float*)d_in[8];
    float* out = (float*)d_out;

    static float *zx = nullptr, *xbc, *Ct, *dt, *dacs, *cb, *st, *pv, *y;
    if (!zx) {
        cudaGetSymbolAddress((void**)&xbc,  g_xbc);
        cudaGetSymbolAddress((void**)&Ct,   g_Ct);
        cudaGetSymbolAddress((void**)&dt,   g_dtv);
        cudaGetSymbolAddress((void**)&dacs, g_dacs);
        cudaGetSymbolAddress((void**)&cb,   g_cb);
        cudaGetSymbolAddress((void**)&st,   g_st);
        cudaGetSymbolAddress((void**)&pv,   g_pv);
        cudaGetSymbolAddress((void**)&y,    g_y);
        cudaGetSymbolAddress((void**)&zx,   g_zx);   // set last: guards the cache
    }

    // 1) in_proj: zx[t, :] = u[t] @ Win^T    (M=4096, N=8512, K=2048)
    gemm_tn<<<dim3(DPROJ / 64, TOK / 128, 1), 256>>>(u, Win, zx,
        DMODEL, DMODEL, DMODEL, DPROJ, 0, 0, 0);

    // 2) dt softplus
    k_dt<<<(TOK * NH + 255) / 256, 256>>>(zx, dtb, dt);

    // 3) conv + silu (+ C^T)
    k_conv<<<(int)(((long)TOK * CDIM + 255) / 256), 256>>>(zx, convw, convb, xbc, Ct);

    // 4) dA cumsum per (chunk, head)
    k_dacs<<<NCC * NH, CK>>>(dt, Alog, dacs);

    // 5) CB^T[cc][s][l] = B[s]·C[l]   (batched M=256,N=256,K=128)
    gemm_tn<<<dim3(CK / 64, CK / 128, NCC), 256>>>(xbc + DINNER, xbc + DINNER + NST, cb,
        NST, CDIM, CDIM, CK, (long)CK * CDIM, (long)CK * CDIM, (long)CK * CK);

    // 6) chunk states
    k_states<<<NCC * NH, 256>>>(xbc, dt, dacs, st);

    // 7) inter-chunk scan
    k_scan<<<2 * NH, 256>>>(st, dacs, pv);

    // 8) Y_diag + Y_off + skip, gated
    k_y<<<NCC * NH, 256>>>(xbc, zx, dt, dacs, cb, Ct, pv, Dsk, y);

    // 9) RMSNorm
    k_rms<<<TOK, 256>>>(y, nw);

    // 10) out_proj: out = y @ Wout^T   (M=4096, N=2048, K=4096)
    gemm_tn<<<dim3(DMODEL / 64, TOK / 128, 1), 256>>>(y, Wout, out,
        DINNER, DINNER, DINNER, DMODEL, 0, 0, 0);
}

// round 2
// speedup vs baseline: 1.8364x; 1.8364x over previous
#include <cuda_runtime.h>

// ---------------- problem constants ----------------
#define TOK    4096        // BATCH*SEQLEN
#define DMODEL 2048
#define DINNER 4096
#define NH     64
#define HD     64
#define NST    128
#define CDIM   4352        // DINNER + 2*NST
#define DPROJ  8512        // 2*DINNER + 2*NST + NH
#define SEQ    2048
#define CK     256         // chunk length
#define NCC    16          // BATCH * (SEQ/CK) total chunks

// ---------------- scratch (device globals; no allocation) ----------------
__device__ __align__(16) float g_zx  [(size_t)TOK*DPROJ];     // in_proj output
__device__ __align__(16) float g_xbc [(size_t)TOK*CDIM];      // conv+silu output
__device__ __align__(16) float g_Ct  [(size_t)NST*TOK];       // C transposed [n][t]
__device__ __align__(16) float g_dtv [(size_t)TOK*NH];        // softplus dt
__device__ __align__(16) float g_dacs[(size_t)NCC*NH*CK];     // cumsum(dt*A)
__device__ __align__(16) float g_cb  [(size_t)NCC*CK*CK];     // CB^T : [cc][s][l]
__device__ __align__(16) float g_st  [(size_t)NCC*NH*HD*NST]; // chunk states
__device__ __align__(16) float g_pv  [(size_t)NCC*NH*HD*NST]; // prefix states
__device__ __align__(16) float g_y   [(size_t)TOK*DINNER];    // gated y

// ---------------- tf32 helpers ----------------
__device__ __forceinline__ unsigned f2tf(float x) {
    unsigned r; asm("cvt.rna.tf32.f32 %0, %1;" : "=r"(r) : "f"(x)); return r;
}
__device__ __forceinline__ void mma_tf32(float& c0, float& c1, float& c2, float& c3,
                                         unsigned a0, unsigned a1, unsigned a2, unsigned a3,
                                         unsigned b0, unsigned b1) {
    asm volatile("mma.sync.aligned.m16n8k8.row.col.f32.tf32.tf32.f32 "
                 "{%0,%1,%2,%3}, {%4,%5,%6,%7}, {%8,%9}, {%0,%1,%2,%3};"
                 : "+f"(c0), "+f"(c1), "+f"(c2), "+f"(c3)
                 : "r"(a0), "r"(a1), "r"(a2), "r"(a3), "r"(b0), "r"(b1));
}

// ---------------- tf32 tensor-core GEMM: C[m,n] = sum_k A[m,k]*B[n,k] ----------------
// BM=128, BN=64, BK=16, 256 threads (8 warps), warp tile 32x32 via m16n8k8.
#define ASTR 20   // smem row stride (floats) — conflict-free for frag pattern, 16B aligned
__global__ __launch_bounds__(256) void gemm_tf32(
    const float* __restrict__ A, const float* __restrict__ B, float* __restrict__ C,
    int K, int lda, int ldb, int ldc, long aB, long bB, long cB)
{
    const float* Ab = A + (long)blockIdx.z * aB;
    const float* Bb = B + (long)blockIdx.z * bB;
    float*       Cb = C + (long)blockIdx.z * cB;

    __shared__ unsigned As[128 * ASTR];
    __shared__ unsigned Bs[64 * ASTR];

    int tid  = threadIdx.x;
    int wid  = tid >> 5, lane = tid & 31;
    int g    = lane >> 2, tig = lane & 3;
    int wm   = wid & 3, wn = wid >> 2;          // 4 m-warps x 2 n-warps
    int m0   = blockIdx.y * 128, n0 = blockIdx.x * 64;

    // global-load assignments
    int aRow = tid >> 1, aCol = (tid & 1) * 8;  // each thread: 8 contiguous k of one A row
    int bRow = tid >> 2, bCol = (tid & 3) * 4;  // each thread: 4 contiguous k of one B row
    const float* aptr = Ab + (long)(m0 + aRow) * lda + aCol;
    const float* bptr = Bb + (long)(n0 + bRow) * ldb + bCol;

    float acc[2][4][4];
#pragma unroll
    for (int i = 0; i < 2; i++)
#pragma unroll
        for (int j = 0; j < 4; j++)
#pragma unroll
            for (int r = 0; r < 4; r++) acc[i][j][r] = 0.f;

    float4 ra0 = *(const float4*)(aptr);
    float4 ra1 = *(const float4*)(aptr + 4);
    float4 rb  = *(const float4*)(bptr);

    for (int k0 = 0; k0 < K; k0 += 16) {
        // store current tile (converted to tf32)
        unsigned* as = As + aRow * ASTR + aCol;
        as[0] = f2tf(ra0.x); as[1] = f2tf(ra0.y); as[2] = f2tf(ra0.z); as[3] = f2tf(ra0.w);
        as[4] = f2tf(ra1.x); as[5] = f2tf(ra1.y); as[6] = f2tf(ra1.z); as[7] = f2tf(ra1.w);
        unsigned* bs = Bs + bRow * ASTR + bCol;
        bs[0] = f2tf(rb.x); bs[1] = f2tf(rb.y); bs[2] = f2tf(rb.z); bs[3] = f2tf(rb.w);
        __syncthreads();

        // prefetch next tile into registers
        if (k0 + 16 < K) {
            ra0 = *(const float4*)(aptr + k0 + 16);
            ra1 = *(const float4*)(aptr + k0 + 20);
            rb  = *(const float4*)(bptr + k0 + 16);
        }

        // compute
#pragma unroll
        for (int ks = 0; ks < 2; ks++) {
            int kb = ks * 8;
            unsigned bf[4][2];
#pragma unroll
            for (int nt = 0; nt < 4; nt++) {
                const unsigned* bp = Bs + (wn * 32 + nt * 8 + g) * ASTR + kb;
                bf[nt][0] = bp[tig]; bf[nt][1] = bp[tig + 4];
            }
#pragma unroll
            for (int mt = 0; mt < 2; mt++) {
                const unsigned* ap0 = As + (wm * 32 + mt * 16 + g) * ASTR + kb;
                const unsigned* ap1 = ap0 + 8 * ASTR;
                unsigned a0 = ap0[tig], a2 = ap0[tig + 4];
                unsigned a1 = ap1[tig], a3 = ap1[tig + 4];
#pragma unroll
                for (int nt = 0; nt < 4; nt++)
                    mma_tf32(acc[mt][nt][0], acc[mt][nt][1], acc[mt][nt][2], acc[mt][nt][3],
                             a0, a1, a2, a3, bf[nt][0], bf[nt][1]);
            }
        }
        __syncthreads();
    }

    // epilogue: c0,c1 at (row, 2*tig), c2,c3 at (row+8, 2*tig)
#pragma unroll
    for (int mt = 0; mt < 2; mt++) {
#pragma unroll
        for (int nt = 0; nt < 4; nt++) {
            int row = m0 + wm * 32 + mt * 16 + g;
            int col = n0 + wn * 32 + nt * 8 + tig * 2;
            float2* p0 = (float2*)(Cb + (long)row * ldc + col);
            float2* p1 = (float2*)(Cb + (long)(row + 8) * ldc + col);
            *p0 = make_float2(acc[mt][nt][0], acc[mt][nt][1]);
            *p1 = make_float2(acc[mt][nt][2], acc[mt][nt][3]);
        }
    }
}

// ---------------- dt = softplus(raw + bias) ----------------
__global__ void k_dt(const float* __restrict__ zx, const float* __restrict__ dt_bias,
                     float* __restrict__ dt)
{
    int i = blockIdx.x * 256 + threadIdx.x;
    if (i >= TOK * NH) return;
    int t = i >> 6, h = i & 63;
    float v = zx[(long)t * DPROJ + (DINNER + CDIM) + h] + dt_bias[h];
    dt[i] = (v > 20.f) ? v : log1pf(expf(v));
}

// ---------------- causal conv1d(width 4) + bias + silu; also emit C^T ----------------
__global__ void k_conv(const float* __restrict__ zx, const float* __restrict__ w,
                       const float* __restrict__ bias, float* __restrict__ xbc,
                       float* __restrict__ Ct)
{
    long i = (long)blockIdx.x * 256 + threadIdx.x;
    if (i >= (long)TOK * CDIM) return;
    int t = (int)(i / CDIM), c = (int)(i % CDIM);
    int l = t & (SEQ - 1);
    float acc = bias[c];
#pragma unroll
    for (int k = 0; k < 4; k++) {
        int lt = l - 3 + k;
        if (lt >= 0)
            acc = fmaf(w[c * 4 + k], zx[(long)(t - 3 + k) * DPROJ + DINNER + c], acc);
    }
    float s = acc / (1.f + expf(-acc));
    xbc[i] = s;
    int n = c - (DINNER + NST);
    if (n >= 0) Ct[(long)n * TOK + t] = s;
}

// ---------------- per-(chunk,head) cumsum of dt*A ----------------
__global__ void k_dacs(const float* __restrict__ dt, const float* __restrict__ Alog,
                       float* __restrict__ dacs)
{
    int cc = blockIdx.x >> 6, h = blockIdx.x & 63;
    int s = threadIdx.x;
    int t = cc * CK + s;
    float a = -expf(Alog[h]);
    float v = dt[t * NH + h] * a;
    __shared__ float sm[CK];
    sm[s] = v; __syncthreads();
    for (int off = 1; off < CK; off <<= 1) {
        float tv = (s >= off) ? sm[s - off] : 0.f;
        __syncthreads();
        sm[s] += tv;
        __syncthreads();
    }
    dacs[(blockIdx.x << 8) + s] = sm[s];
}

// ---------------- states[h,p,n] = sum_s B[s,n]*exp(dAcs[255]-dAcs[s])*x[s,p]*dt[s] ----------------
__global__ __launch_bounds__(256) void k_states(const float* __restrict__ xbc,
        const float* __restrict__ dt, const float* __restrict__ dacs, float* __restrict__ st)
{
    int cc = blockIdx.x >> 6, h = blockIdx.x & 63;
    int tb = cc * CK;
    const float* dA = dacs + (blockIdx.x << 8);
    float dlast = dA[CK - 1];
    int tid = threadIdx.x;
    int p = tid & 63, ng = tid >> 6;

    float acc[32];
#pragma unroll
    for (int j = 0; j < 32; j++) acc[j] = 0.f;

    __shared__ float sx[32][64];
    __shared__ float sb[32][128];
    for (int s0 = 0; s0 < CK; s0 += 32) {
        for (int i = tid; i < 32 * 64; i += 256) {
            int sl = i >> 6, pp = i & 63;
            int t = tb + s0 + sl;
            sx[sl][pp] = xbc[(long)t * CDIM + h * HD + pp] * dt[t * NH + h];
        }
        for (int i = tid; i < 32 * 128; i += 256) {
            int sl = i >> 7, nn = i & 127;
            int t = tb + s0 + sl;
            sb[sl][nn] = xbc[(long)t * CDIM + DINNER + nn] * __expf(dlast - dA[s0 + sl]);
        }
        __syncthreads();
#pragma unroll 4
        for (int sl = 0; sl < 32; sl++) {
            float a = sx[sl][p];
#pragma unroll
            for (int j = 0; j < 32; j++) acc[j] = fmaf(a, sb[sl][ng * 32 + j], acc[j]);
        }
        __syncthreads();
    }
    float* o = st + ((long)blockIdx.x << 13) + p * NST + ng * 32;
#pragma unroll
    for (int j = 0; j < 32; j += 4)
        *(float4*)(o + j) = make_float4(acc[j], acc[j + 1], acc[j + 2], acc[j + 3]);
}

// ---------------- sequential chunk scan (8 chunks per batch) ----------------
__global__ void k_scan(const float* __restrict__ st, const float* __restrict__ dacs,
                       float* __restrict__ pv)
{
    int b = blockIdx.x >> 6, h = blockIdx.x & 63;
    int tid = threadIdx.x;
    float carry[32];
#pragma unroll
    for (int j = 0; j < 32; j++) carry[j] = 0.f;
    for (int c = 0; c < 8; c++) {
        int cc = b * 8 + c;
        long base = ((long)(cc * 64 + h)) << 13;
        float dec = __expf(dacs[((cc * 64 + h) << 8) + CK - 1]);
#pragma unroll
        for (int j = 0; j < 32; j++) {
            long e = base + tid + j * 256;
            pv[e] = carry[j];
            carry[j] = carry[j] * dec + st[e];
        }
    }
}

// ---------------- Y = Y_diag + Y_off + D*x, gated by silu(z) ----------------
__global__ __launch_bounds__(256) void k_y(const float* __restrict__ xbc,
        const float* __restrict__ zx, const float* __restrict__ dt,
        const float* __restrict__ dacs, const float* __restrict__ cb,
        const float* __restrict__ Ct, const float* __restrict__ pv,
        const float* __restrict__ Dsk, float* __restrict__ y)
{
    int cc = blockIdx.x >> 6, h = blockIdx.x & 63;
    int l = threadIdx.x;
    int tb = cc * CK;
    int t = tb + l;
    const float* dA = dacs + (blockIdx.x << 8);
    float dAl = dA[l];

    float acc[64];
#pragma unroll
    for (int p = 0; p < 64; p++) acc[p] = 0.f;

    __shared__ float sbuf[64 * 128];
    __shared__ float sdas[64];
    const float* cbb = cb + ((long)cc << 16);

    // ---- pass A: Y_diag (masked, s <= l) ----
    for (int s0 = 0; s0 < CK; s0 += 64) {
        for (int i = threadIdx.x; i < 64 * 64; i += 256) {
            int sl = i >> 6, pp = i & 63;
            int ts = tb + s0 + sl;
            sbuf[sl * 64 + pp] = xbc[(long)ts * CDIM + h * HD + pp] * dt[ts * NH + h];
        }
        if (threadIdx.x < 64) sdas[threadIdx.x] = dA[s0 + threadIdx.x];
        __syncthreads();
        if (s0 <= l) {
            int smax = min(64, l - s0 + 1);
            for (int sl = 0; sl < smax; sl++) {
                float w = __expf(dAl - sdas[sl]) * cbb[((s0 + sl) << 8) + l];
                const float4* r4 = (const float4*)(sbuf + sl * 64);
#pragma unroll
                for (int p4 = 0; p4 < 16; p4++) {
                    float4 v = r4[p4];
                    acc[p4 * 4 + 0] = fmaf(w, v.x, acc[p4 * 4 + 0]);
                    acc[p4 * 4 + 1] = fmaf(w, v.y, acc[p4 * 4 + 1]);
                    acc[p4 * 4 + 2] = fmaf(w, v.z, acc[p4 * 4 + 2]);
                    acc[p4 * 4 + 3] = fmaf(w, v.w, acc[p4 * 4 + 3]);
                }
            }
        }
        __syncthreads();
    }

    // ---- pass B: Y_off via prev-state staged in smem ----
    const float* pvb = pv + ((long)blockIdx.x << 13);
    for (int i = threadIdx.x; i < 8192; i += 256) sbuf[i] = pvb[i];
    __syncthreads();
    float el = __expf(dAl);
    const float4* pb4 = (const float4*)sbuf;
    for (int n4 = 0; n4 < 32; n4++) {
        float c0 = Ct[(long)(n4 * 4 + 0) * TOK + t] * el;
        float c1 = Ct[(long)(n4 * 4 + 1) * TOK + t] * el;
        float c2 = Ct[(long)(n4 * 4 + 2) * TOK + t] * el;
        float c3 = Ct[(long)(n4 * 4 + 3) * TOK + t] * el;
#pragma unroll
        for (int p = 0; p < 64; p++) {
            float4 v = pb4[p * 32 + n4];
            acc[p] = fmaf(c0, v.x, fmaf(c1, v.y, fmaf(c2, v.z, fmaf(c3, v.w, acc[p]))));
        }
    }

    // ---- epilogue ----
    float dsk = Dsk[h];
    const float4* xr = (const float4*)(xbc + (long)t * CDIM + h * HD);
    const float4* zr = (const float4*)(zx + (long)t * DPROJ + h * HD);
    float4* yr = (float4*)(y + (long)t * DINNER + h * HD);
#pragma unroll
    for (int p4 = 0; p4 < 16; p4++) {
        float4 xv = xr[p4], zv = zr[p4], o;
        float yv;
        yv = acc[p4 * 4 + 0] + xv.x * dsk; o.x = yv * (zv.x / (1.f + expf(-zv.x)));
        yv = acc[p4 * 4 + 1] + xv.y * dsk; o.y = yv * (zv.y / (1.f + expf(-zv.y)));
        yv = acc[p4 * 4 + 2] + xv.z * dsk; o.z = yv * (zv.z / (1.f + expf(-zv.z)));
        yv = acc[p4 * 4 + 3] + xv.w * dsk; o.w = yv * (zv.w / (1.f + expf(-zv.w)));
        yr[p4] = o;
    }
}

// ---------------- RMSNorm over full D_INNER ----------------
__global__ void k_rms(float* __restrict__ y, const float* __restrict__ nw)
{
    int t = blockIdx.x;
    float* row = y + (long)t * DINNER;
    float ss = 0.f;
    for (int i = threadIdx.x; i < DINNER; i += 256) { float v = row[i]; ss = fmaf(v, v, ss); }
    __shared__ float red[256];
    red[threadIdx.x] = ss; __syncthreads();
    for (int o = 128; o > 0; o >>= 1) {
        if (threadIdx.x < o) red[threadIdx.x] += red[threadIdx.x + o];
        __syncthreads();
    }
    float sc = rsqrtf(red[0] / (float)DINNER + 1e-5f);
    for (int i = threadIdx.x; i < DINNER; i += 256) row[i] = row[i] * sc * nw[i];
}

// ---------------- launch ----------------
extern "C" void kernel_launch(void* const* d_in, const int* in_sizes, int n_in,
                              void* d_out, int out_size)
{
    const float* u     = (const float*)d_in[0];
    const float* Win   = (const float*)d_in[1];
    const float* convw = (const float*)d_in[2];
    const float* convb = (const float*)d_in[3];
    const float* dtb   = (const float*)d_in[4];
    const float* Alog  = (const float*)d_in[5];
    const float* Dsk   = (const float*)d_in[6];
    const float* nw    = (const float*)d_in[7];
    const float* Wout  = (const float*)d_in[8];
    float* out = (float*)d_out;

    static float *zx = nullptr, *xbc, *Ct, *dt, *dacs, *cb, *st, *pv, *y;
    if (!zx) {
        cudaGetSymbolAddress((void**)&xbc,  g_xbc);
        cudaGetSymbolAddress((void**)&Ct,   g_Ct);
        cudaGetSymbolAddress((void**)&dt,   g_dtv);
        cudaGetSymbolAddress((void**)&dacs, g_dacs);
        cudaGetSymbolAddress((void**)&cb,   g_cb);
        cudaGetSymbolAddress((void**)&st,   g_st);
        cudaGetSymbolAddress((void**)&pv,   g_pv);
        cudaGetSymbolAddress((void**)&y,    g_y);
        cudaGetSymbolAddress((void**)&zx,   g_zx);
    }

    // 1) in_proj: zx = u @ Win^T   (M=4096, N=8512, K=2048)
    gemm_tf32<<<dim3(DPROJ / 64, TOK / 128, 1), 256>>>(u, Win, zx,
        DMODEL, DMODEL, DMODEL, DPROJ, 0, 0, 0);

    // 2) dt softplus
    k_dt<<<(TOK * NH + 255) / 256, 256>>>(zx, dtb, dt);

    // 3) conv + silu (+ C^T)
    k_conv<<<(int)(((long)TOK * CDIM + 255) / 256), 256>>>(zx, convw, convb, xbc, Ct);

    // 4) dA cumsum
    k_dacs<<<NCC * NH, CK>>>(dt, Alog, dacs);

    // 5) CB^T[cc][s][l] = B[s]·C[l]   (batched M=256,N=256,K=128)
    gemm_tf32<<<dim3(CK / 64, CK / 128, NCC), 256>>>(xbc + DINNER, xbc + DINNER + NST, cb,
        NST, CDIM, CDIM, CK, (long)CK * CDIM, (long)CK * CDIM, (long)CK * CK);

    // 6) chunk states
    k_states<<<NCC * NH, 256>>>(xbc, dt, dacs, st);

    // 7) inter-chunk scan
    k_scan<<<2 * NH, 256>>>(st, dacs, pv);

    // 8) Y_diag + Y_off + skip, gated
    k_y<<<NCC * NH, 256>>>(xbc, zx, dt, dacs, cb, Ct, pv, Dsk, y);

    // 9) RMSNorm
    k_rms<<<TOK, 256>>>(y, nw);

    // 10) out_proj: out = y @ Wout^T  (M=4096, N=2048, K=4096)
    gemm_tf32<<<dim3(DMODEL / 64, TOK / 128, 1), 256>>>(y, Wout, out,
        DINNER, DINNER, DINNER, DMODEL, 0, 0, 0);
}